// round 7
// baseline (speedup 1.0000x reference)
#include <cuda_runtime.h>
#include <math.h>
#include <stdint.h>

#define VOCAB 32000
#define DIM   1024
#define NBITS 15
#define NTOK  4096
#define KDIM  1024

#define OFF_BIT   4194304u
#define OFF_LOGIT 8388608u
#define OFF_LW    (8388608u + 131072000u)

// ---------------------------------------------------------------------------
// 1) id_emb: gather weight rows. float4 vectorized.
// ---------------------------------------------------------------------------
__global__ void id_embed_kernel(const int* __restrict__ ids,
                                const float* __restrict__ weight,
                                float* __restrict__ out)
{
    int idx = blockIdx.x * blockDim.x + threadIdx.x;
    int token = idx >> 8;
    int d4    = idx & 255;
    int id    = ids[token];
    id = min(max(id, 0), VOCAB - 1);
    const float4* src = reinterpret_cast<const float4*>(weight + (size_t)id * DIM);
    reinterpret_cast<float4*>(out)[idx] = src[d4];
}

// ---------------------------------------------------------------------------
// 2) bit_emb: sum_j sign_j(id) * weight_bit[j]. MSB-first.
// ---------------------------------------------------------------------------
__global__ void bit_embed_kernel(const int* __restrict__ ids,
                                 const float* __restrict__ wbit,
                                 float* __restrict__ out)
{
    int idx = blockIdx.x * blockDim.x + threadIdx.x;
    int token = idx >> 8;
    int d4    = idx & 255;
    int id    = ids[token];
    id = min(max(id, 0), VOCAB - 1);
    const float4* wb = reinterpret_cast<const float4*>(wbit);
    float4 acc = make_float4(0.f, 0.f, 0.f, 0.f);
#pragma unroll
    for (int j = 0; j < NBITS; j++) {
        float4 w = wb[j * 256 + d4];
        float s = ((id >> (14 - j)) & 1) ? 1.0f : -1.0f;
        acc.x += s * w.x; acc.y += s * w.y; acc.z += s * w.z; acc.w += s * w.w;
    }
    reinterpret_cast<float4*>(out)[idx] = acc;
}

// ---------------------------------------------------------------------------
// 3) logit = tensor @ weight^T via 3xTF32 split-precision mma.sync.
//    C += Ahi*Bhi + Ahi*Blo + Alo*Bhi  -> ~fp32 accuracy on tensor cores.
//    Block 128x128, BK=8, 8 warps (warp tile 64x32), m16n8k8 atoms.
//    SMEM stride 12 floats: 16B-aligned STS, conflict-free fragment LDS.
// ---------------------------------------------------------------------------
#define BKS     8
#define SSTRIDE 12   // 8 data + 4 pad floats per row

__device__ __forceinline__ uint32_t f2tf32(float f) {
    uint32_t u;
    asm("cvt.rna.tf32.f32 %0, %1;" : "=r"(u) : "f"(f));
    return u;
}

__device__ __forceinline__ void mma_tf32(float* c, const uint32_t* a, const uint32_t* b) {
    asm volatile(
        "mma.sync.aligned.m16n8k8.row.col.f32.tf32.tf32.f32 "
        "{%0,%1,%2,%3},{%4,%5,%6,%7},{%8,%9},{%0,%1,%2,%3};"
        : "+f"(c[0]), "+f"(c[1]), "+f"(c[2]), "+f"(c[3])
        : "r"(a[0]), "r"(a[1]), "r"(a[2]), "r"(a[3]), "r"(b[0]), "r"(b[1]));
}

// split v into hi (tf32 bits, also exact fp32) and lo = tf32(v - hi)
__device__ __forceinline__ void split_tf32(float v, uint32_t& hi, uint32_t& lo) {
    hi = f2tf32(v);
    float hf = __uint_as_float(hi);
    lo = f2tf32(v - hf);
}

__global__ __launch_bounds__(256)
void tf32x3_gemm_nt_kernel(const float* __restrict__ A,   // [4096, 1024]
                           const float* __restrict__ B,   // [32000, 1024]
                           float* __restrict__ C)         // [4096, 32000]
{
    __shared__ __align__(16) uint32_t Ah[2][128 * SSTRIDE];
    __shared__ __align__(16) uint32_t Al[2][128 * SSTRIDE];
    __shared__ __align__(16) uint32_t Bh[2][128 * SSTRIDE];
    __shared__ __align__(16) uint32_t Bl[2][128 * SSTRIDE];

    const int tid  = threadIdx.x;
    const int lane = tid & 31;
    const int warp = tid >> 5;
    const int wm   = (warp & 1) * 64;
    const int wn   = (warp >> 1) * 32;
    const int g    = lane >> 2;    // 0..7
    const int t    = lane & 3;     // 0..3

    const int mBase = blockIdx.y * 128;
    const int nBase = blockIdx.x * 128;

    // Staging: thread -> (row = tid>>1 in 0..127, col4 = (tid&1)*4)
    const int r0 = tid >> 1, c0 = (tid & 1) * 4;
    const float* Ag = A + (size_t)(mBase + r0) * KDIM + c0;
    const float* Bg = B + (size_t)(nBase + r0) * KDIM + c0;
    const int sOff = r0 * SSTRIDE + c0;

    float acc[4][4][4];
#pragma unroll
    for (int i = 0; i < 4; i++)
#pragma unroll
        for (int j = 0; j < 4; j++)
#pragma unroll
            for (int q = 0; q < 4; q++) acc[i][j][q] = 0.f;

    // prologue: tile 0 -> stage 0
    {
        float4 av = *reinterpret_cast<const float4*>(Ag);
        float4 bv = *reinterpret_cast<const float4*>(Bg);
        uint4 ahv, alv, bhv, blv;
        split_tf32(av.x, ahv.x, alv.x); split_tf32(av.y, ahv.y, alv.y);
        split_tf32(av.z, ahv.z, alv.z); split_tf32(av.w, ahv.w, alv.w);
        split_tf32(bv.x, bhv.x, blv.x); split_tf32(bv.y, bhv.y, blv.y);
        split_tf32(bv.z, bhv.z, blv.z); split_tf32(bv.w, bhv.w, blv.w);
        *reinterpret_cast<uint4*>(&Ah[0][sOff]) = ahv;
        *reinterpret_cast<uint4*>(&Al[0][sOff]) = alv;
        *reinterpret_cast<uint4*>(&Bh[0][sOff]) = bhv;
        *reinterpret_cast<uint4*>(&Bl[0][sOff]) = blv;
    }
    __syncthreads();

    const int NSTEP = KDIM / BKS;   // 128
    for (int kt = 0; kt < NSTEP; kt++) {
        const int buf = kt & 1;

        float4 av, bv;
        if (kt + 1 < NSTEP) {
            av = *reinterpret_cast<const float4*>(Ag + (kt + 1) * BKS);
            bv = *reinterpret_cast<const float4*>(Bg + (kt + 1) * BKS);
        }

        // fragment loads (hi + lo)
        uint32_t afh[4][4], afl[4][4], bfh[4][2], bfl[4][2];
#pragma unroll
        for (int mf = 0; mf < 4; mf++) {
            const int mb = wm + mf * 16;
            const int i0 = (mb + g)     * SSTRIDE + t;
            const int i1 = (mb + g + 8) * SSTRIDE + t;
            afh[mf][0] = Ah[buf][i0];     afh[mf][1] = Ah[buf][i1];
            afh[mf][2] = Ah[buf][i0 + 4]; afh[mf][3] = Ah[buf][i1 + 4];
            afl[mf][0] = Al[buf][i0];     afl[mf][1] = Al[buf][i1];
            afl[mf][2] = Al[buf][i0 + 4]; afl[mf][3] = Al[buf][i1 + 4];
        }
#pragma unroll
        for (int nf = 0; nf < 4; nf++) {
            const int ib = (wn + nf * 8 + g) * SSTRIDE + t;
            bfh[nf][0] = Bh[buf][ib]; bfh[nf][1] = Bh[buf][ib + 4];
            bfl[nf][0] = Bl[buf][ib]; bfl[nf][1] = Bl[buf][ib + 4];
        }

        // 3-pass mma
#pragma unroll
        for (int mf = 0; mf < 4; mf++)
#pragma unroll
            for (int nf = 0; nf < 4; nf++) {
                mma_tf32(acc[mf][nf], afh[mf], bfh[nf]);
                mma_tf32(acc[mf][nf], afh[mf], bfl[nf]);
                mma_tf32(acc[mf][nf], afl[mf], bfh[nf]);
            }

        if (kt + 1 < NSTEP) {
            const int nb = buf ^ 1;
            uint4 ahv, alv, bhv, blv;
            split_tf32(av.x, ahv.x, alv.x); split_tf32(av.y, ahv.y, alv.y);
            split_tf32(av.z, ahv.z, alv.z); split_tf32(av.w, ahv.w, alv.w);
            split_tf32(bv.x, bhv.x, blv.x); split_tf32(bv.y, bhv.y, blv.y);
            split_tf32(bv.z, bhv.z, blv.z); split_tf32(bv.w, bhv.w, blv.w);
            __syncthreads();   // all warps done reading stage nb (from kt-1)
            *reinterpret_cast<uint4*>(&Ah[nb][sOff]) = ahv;
            *reinterpret_cast<uint4*>(&Al[nb][sOff]) = alv;
            *reinterpret_cast<uint4*>(&Bh[nb][sOff]) = bhv;
            *reinterpret_cast<uint4*>(&Bl[nb][sOff]) = blv;
            __syncthreads();
        }
    }

    // epilogue: atom layout c0:(g,2t) c1:(g,2t+1) c2:(g+8,2t) c3:(g+8,2t+1)
#pragma unroll
    for (int mf = 0; mf < 4; mf++) {
#pragma unroll
        for (int nf = 0; nf < 4; nf++) {
            const int row = mBase + wm + mf * 16 + g;
            const int col = nBase + wn + nf * 8 + t * 2;
            float* p0 = C + (size_t)row * VOCAB + col;
            float* p1 = C + (size_t)(row + 8) * VOCAB + col;
            *reinterpret_cast<float2*>(p0) = make_float2(acc[mf][nf][0], acc[mf][nf][1]);
            *reinterpret_cast<float2*>(p1) = make_float2(acc[mf][nf][2], acc[mf][nf][3]);
        }
    }
}

// ---------------------------------------------------------------------------
// 4) logit_w: softmax over 32000 + projection onto +-1 bit codes.
// ---------------------------------------------------------------------------
__global__ __launch_bounds__(256)
void softmax_bits_kernel(const float* __restrict__ logit,
                         float* __restrict__ out_lw)
{
    const int row = blockIdx.x;
    const int tid = threadIdx.x;
    const float* L = logit + (size_t)row * VOCAB;

    float m = -1e30f;
    for (int i = tid; i < VOCAB; i += 256) m = fmaxf(m, L[i]);
#pragma unroll
    for (int o = 16; o; o >>= 1) m = fmaxf(m, __shfl_xor_sync(0xffffffffu, m, o));
    __shared__ float wmax[8];
    if ((tid & 31) == 0) wmax[tid >> 5] = m;
    __syncthreads();
    m = wmax[0];
#pragma unroll
    for (int w = 1; w < 8; w++) m = fmaxf(m, wmax[w]);

    float s = 0.f;
    float bh[7] = {0.f, 0.f, 0.f, 0.f, 0.f, 0.f, 0.f};
    for (int t = 0; t < VOCAB / 256; t++) {
        float e = __expf(L[tid + (t << 8)] - m);
        s += e;
#pragma unroll
        for (int k = 0; k < 7; k++)
            bh[k] += ((t >> k) & 1) ? e : 0.f;
    }

    float bs[16];
#pragma unroll
    for (int k = 0; k < 8; k++) bs[k] = ((tid >> k) & 1) ? s : 0.f;
#pragma unroll
    for (int k = 0; k < 7; k++) bs[k + 8] = bh[k];
    bs[15] = s;

#pragma unroll
    for (int q = 0; q < 16; q++) {
#pragma unroll
        for (int o = 16; o; o >>= 1)
            bs[q] += __shfl_xor_sync(0xffffffffu, bs[q], o);
    }
    __shared__ float red[8][16];
    if ((tid & 31) == 0) {
#pragma unroll
        for (int q = 0; q < 16; q++) red[tid >> 5][q] = bs[q];
    }
    __syncthreads();
    if (tid == 0) {
        float tot[16];
#pragma unroll
        for (int q = 0; q < 16; q++) {
            float v = 0.f;
#pragma unroll
            for (int w = 0; w < 8; w++) v += red[w][q];
            tot[q] = v;
        }
        float inv = 1.0f / tot[15];
#pragma unroll
        for (int k = 0; k < 15; k++)
            out_lw[(size_t)row * NBITS + (14 - k)] = 2.0f * tot[k] * inv - 1.0f;
    }
}

// ---------------------------------------------------------------------------
extern "C" void kernel_launch(void* const* d_in, const int* in_sizes, int n_in,
                              void* d_out, int out_size)
{
    const int*   ids    = (const int*)  d_in[0];
    const float* tensor = (const float*)d_in[1];
    const float* weight = (const float*)d_in[2];
    const float* wbit   = (const float*)d_in[3];

    float* out     = (float*)d_out;
    float* id_emb  = out;
    float* bit_emb = out + OFF_BIT;
    float* logit   = out + OFF_LOGIT;
    float* lw      = out + OFF_LW;

    id_embed_kernel <<<4096, 256>>>(ids, weight, id_emb);
    bit_embed_kernel<<<4096, 256>>>(ids, wbit, bit_emb);

    dim3 grid(VOCAB / 128, NTOK / 128);   // 250 x 32
    tf32x3_gemm_nt_kernel<<<grid, 256>>>(tensor, weight, logit);

    softmax_bits_kernel<<<NTOK, 256>>>(logit, lw);
}

// round 8
// speedup vs baseline: 3.5350x; 3.5350x over previous
#include <cuda_runtime.h>
#include <math.h>
#include <stdint.h>

#define VOCAB 32000
#define DIM   1024
#define NBITS 15
#define NTOK  4096
#define KDIM  1024

#define OFF_BIT   4194304u
#define OFF_LOGIT 8388608u
#define OFF_LW    (8388608u + 131072000u)

// ---------------------------------------------------------------------------
// 1) id_emb: gather weight rows. float4 vectorized.
// ---------------------------------------------------------------------------
__global__ void id_embed_kernel(const int* __restrict__ ids,
                                const float* __restrict__ weight,
                                float* __restrict__ out)
{
    int idx = blockIdx.x * blockDim.x + threadIdx.x;
    int token = idx >> 8;
    int d4    = idx & 255;
    int id    = ids[token];
    id = min(max(id, 0), VOCAB - 1);
    const float4* src = reinterpret_cast<const float4*>(weight + (size_t)id * DIM);
    reinterpret_cast<float4*>(out)[idx] = src[d4];
}

// ---------------------------------------------------------------------------
// 2) bit_emb: sum_j sign_j(id) * weight_bit[j]. MSB-first.
// ---------------------------------------------------------------------------
__global__ void bit_embed_kernel(const int* __restrict__ ids,
                                 const float* __restrict__ wbit,
                                 float* __restrict__ out)
{
    int idx = blockIdx.x * blockDim.x + threadIdx.x;
    int token = idx >> 8;
    int d4    = idx & 255;
    int id    = ids[token];
    id = min(max(id, 0), VOCAB - 1);
    const float4* wb = reinterpret_cast<const float4*>(wbit);
    float4 acc = make_float4(0.f, 0.f, 0.f, 0.f);
#pragma unroll
    for (int j = 0; j < NBITS; j++) {
        float4 w = wb[j * 256 + d4];
        float s = ((id >> (14 - j)) & 1) ? 1.0f : -1.0f;
        acc.x += s * w.x; acc.y += s * w.y; acc.z += s * w.z; acc.w += s * w.w;
    }
    reinterpret_cast<float4*>(out)[idx] = acc;
}

// ---------------------------------------------------------------------------
// 3) logit = tensor @ weight^T via 3-pass split-bf16 mma (m16n8k16).
//    v = hi + lo (bf16 each, ~16 mantissa bits total);
//    C += Ah*Bh + Ah*Bl + Al*Bh   (lo*lo term ~2^-18, dropped).
//    Block 128x128, BK=16, 8 warps (warp tile 64x32).
//    SMEM holds bf16x2 pairs as u32, row stride 12 u32 (conflict-free).
// ---------------------------------------------------------------------------
#define BKP     8    // u32 pairs per row per k-tile (BK=16 bf16)
#define SSTR    12   // u32 stride per row (8 data + 4 pad)

__device__ __forceinline__ uint32_t cvt_bf16x2(float hi, float lo) {
    uint32_t u;
    asm("cvt.rn.bf16x2.f32 %0, %1, %2;" : "=r"(u) : "f"(hi), "f"(lo));
    return u;
}

// pack float4 (k-consecutive) into hi-pair/lo-pair u32s
__device__ __forceinline__ void split4(float4 v, uint2& h, uint2& l) {
    h.x = cvt_bf16x2(v.y, v.x);
    h.y = cvt_bf16x2(v.w, v.z);
    float f0 = __uint_as_float(h.x << 16);
    float f1 = __uint_as_float(h.x & 0xffff0000u);
    float f2 = __uint_as_float(h.y << 16);
    float f3 = __uint_as_float(h.y & 0xffff0000u);
    l.x = cvt_bf16x2(v.y - f1, v.x - f0);
    l.y = cvt_bf16x2(v.w - f3, v.z - f2);
}

__device__ __forceinline__ void mma_bf16(float* c, const uint32_t* a, const uint32_t* b) {
    asm volatile(
        "mma.sync.aligned.m16n8k16.row.col.f32.bf16.bf16.f32 "
        "{%0,%1,%2,%3},{%4,%5,%6,%7},{%8,%9},{%0,%1,%2,%3};"
        : "+f"(c[0]), "+f"(c[1]), "+f"(c[2]), "+f"(c[3])
        : "r"(a[0]), "r"(a[1]), "r"(a[2]), "r"(a[3]), "r"(b[0]), "r"(b[1]));
}

__global__ __launch_bounds__(256)
void bf16x3_gemm_nt_kernel(const float* __restrict__ A,   // [4096, 1024]
                           const float* __restrict__ B,   // [32000, 1024]
                           float* __restrict__ C)         // [4096, 32000]
{
    __shared__ __align__(16) uint32_t Ah[2][128 * SSTR];
    __shared__ __align__(16) uint32_t Al[2][128 * SSTR];
    __shared__ __align__(16) uint32_t Bh[2][128 * SSTR];
    __shared__ __align__(16) uint32_t Bl[2][128 * SSTR];

    const int tid  = threadIdx.x;
    const int lane = tid & 31;
    const int warp = tid >> 5;
    const int wm   = (warp & 1) * 64;
    const int wn   = (warp >> 1) * 32;
    const int g    = lane >> 2;    // 0..7
    const int t    = lane & 3;     // 0..3

    const int mBase = blockIdx.y * 128;
    const int nBase = blockIdx.x * 128;

    // Staging: 512 float4-chunks per operand per k-tile; thread owns chunks
    // tid and tid+256. chunk c -> row = c>>2, k4 = (c&3)*4 floats.
    const int row0 = tid >> 2;          // 0..63
    const int c4   = tid & 3;
    const float* Ag0 = A + (size_t)(mBase + row0) * KDIM + c4 * 4;
    const float* Ag1 = A + (size_t)(mBase + row0 + 64) * KDIM + c4 * 4;
    const float* Bg0 = B + (size_t)(nBase + row0) * KDIM + c4 * 4;
    const float* Bg1 = B + (size_t)(nBase + row0 + 64) * KDIM + c4 * 4;
    const int s0 = row0 * SSTR + c4 * 2;
    const int s1 = (row0 + 64) * SSTR + c4 * 2;

    float acc[4][4][4];
#pragma unroll
    for (int i = 0; i < 4; i++)
#pragma unroll
        for (int j = 0; j < 4; j++)
#pragma unroll
            for (int q = 0; q < 4; q++) acc[i][j][q] = 0.f;

    // prologue: k-tile 0 -> stage 0
    {
        float4 a0 = *reinterpret_cast<const float4*>(Ag0);
        float4 a1 = *reinterpret_cast<const float4*>(Ag1);
        float4 b0 = *reinterpret_cast<const float4*>(Bg0);
        float4 b1 = *reinterpret_cast<const float4*>(Bg1);
        uint2 h, l;
        split4(a0, h, l);
        *reinterpret_cast<uint2*>(&Ah[0][s0]) = h; *reinterpret_cast<uint2*>(&Al[0][s0]) = l;
        split4(a1, h, l);
        *reinterpret_cast<uint2*>(&Ah[0][s1]) = h; *reinterpret_cast<uint2*>(&Al[0][s1]) = l;
        split4(b0, h, l);
        *reinterpret_cast<uint2*>(&Bh[0][s0]) = h; *reinterpret_cast<uint2*>(&Bl[0][s0]) = l;
        split4(b1, h, l);
        *reinterpret_cast<uint2*>(&Bh[0][s1]) = h; *reinterpret_cast<uint2*>(&Bl[0][s1]) = l;
    }
    __syncthreads();

    const int NSTEP = KDIM / 16;   // 64
    for (int kt = 0; kt < NSTEP; kt++) {
        const int buf = kt & 1;

        float4 a0, a1, b0, b1;
        if (kt + 1 < NSTEP) {
            const int ko = (kt + 1) * 16;
            a0 = *reinterpret_cast<const float4*>(Ag0 + ko);
            a1 = *reinterpret_cast<const float4*>(Ag1 + ko);
            b0 = *reinterpret_cast<const float4*>(Bg0 + ko);
            b1 = *reinterpret_cast<const float4*>(Bg1 + ko);
        }

        // fragment loads: each reg is one u32 (bf16 pair along k)
        uint32_t afh[4][4], afl[4][4], bfh[4][2], bfl[4][2];
#pragma unroll
        for (int mf = 0; mf < 4; mf++) {
            const int mb = wm + mf * 16;
            const int i0 = (mb + g)     * SSTR + t;
            const int i1 = (mb + g + 8) * SSTR + t;
            afh[mf][0] = Ah[buf][i0];     afh[mf][1] = Ah[buf][i1];
            afh[mf][2] = Ah[buf][i0 + 4]; afh[mf][3] = Ah[buf][i1 + 4];
            afl[mf][0] = Al[buf][i0];     afl[mf][1] = Al[buf][i1];
            afl[mf][2] = Al[buf][i0 + 4]; afl[mf][3] = Al[buf][i1 + 4];
        }
#pragma unroll
        for (int nf = 0; nf < 4; nf++) {
            const int ib = (wn + nf * 8 + g) * SSTR + t;
            bfh[nf][0] = Bh[buf][ib]; bfh[nf][1] = Bh[buf][ib + 4];
            bfl[nf][0] = Bl[buf][ib]; bfl[nf][1] = Bl[buf][ib + 4];
        }

#pragma unroll
        for (int mf = 0; mf < 4; mf++)
#pragma unroll
            for (int nf = 0; nf < 4; nf++) {
                mma_bf16(acc[mf][nf], afh[mf], bfh[nf]);
                mma_bf16(acc[mf][nf], afh[mf], bfl[nf]);
                mma_bf16(acc[mf][nf], afl[mf], bfh[nf]);
            }

        if (kt + 1 < NSTEP) {
            const int nb = buf ^ 1;
            uint2 ha0, la0, ha1, la1, hb0, lb0, hb1, lb1;
            split4(a0, ha0, la0); split4(a1, ha1, la1);
            split4(b0, hb0, lb0); split4(b1, hb1, lb1);
            __syncthreads();   // all warps done reading stage nb (from kt-1)
            *reinterpret_cast<uint2*>(&Ah[nb][s0]) = ha0; *reinterpret_cast<uint2*>(&Al[nb][s0]) = la0;
            *reinterpret_cast<uint2*>(&Ah[nb][s1]) = ha1; *reinterpret_cast<uint2*>(&Al[nb][s1]) = la1;
            *reinterpret_cast<uint2*>(&Bh[nb][s0]) = hb0; *reinterpret_cast<uint2*>(&Bl[nb][s0]) = lb0;
            *reinterpret_cast<uint2*>(&Bh[nb][s1]) = hb1; *reinterpret_cast<uint2*>(&Bl[nb][s1]) = lb1;
            __syncthreads();
        }
    }

    // epilogue: c0:(g,2t) c1:(g,2t+1) c2:(g+8,2t) c3:(g+8,2t+1)
#pragma unroll
    for (int mf = 0; mf < 4; mf++) {
#pragma unroll
        for (int nf = 0; nf < 4; nf++) {
            const int row = mBase + wm + mf * 16 + g;
            const int col = nBase + wn + nf * 8 + t * 2;
            float* p0 = C + (size_t)row * VOCAB + col;
            float* p1 = C + (size_t)(row + 8) * VOCAB + col;
            *reinterpret_cast<float2*>(p0) = make_float2(acc[mf][nf][0], acc[mf][nf][1]);
            *reinterpret_cast<float2*>(p1) = make_float2(acc[mf][nf][2], acc[mf][nf][3]);
        }
    }
}

// ---------------------------------------------------------------------------
// 4) logit_w: softmax over 32000 + projection onto +-1 bit codes.
// ---------------------------------------------------------------------------
__global__ __launch_bounds__(256)
void softmax_bits_kernel(const float* __restrict__ logit,
                         float* __restrict__ out_lw)
{
    const int row = blockIdx.x;
    const int tid = threadIdx.x;
    const float* L = logit + (size_t)row * VOCAB;

    float m = -1e30f;
    for (int i = tid; i < VOCAB; i += 256) m = fmaxf(m, L[i]);
#pragma unroll
    for (int o = 16; o; o >>= 1) m = fmaxf(m, __shfl_xor_sync(0xffffffffu, m, o));
    __shared__ float wmax[8];
    if ((tid & 31) == 0) wmax[tid >> 5] = m;
    __syncthreads();
    m = wmax[0];
#pragma unroll
    for (int w = 1; w < 8; w++) m = fmaxf(m, wmax[w]);

    float s = 0.f;
    float bh[7] = {0.f, 0.f, 0.f, 0.f, 0.f, 0.f, 0.f};
    for (int t = 0; t < VOCAB / 256; t++) {
        float e = __expf(L[tid + (t << 8)] - m);
        s += e;
#pragma unroll
        for (int k = 0; k < 7; k++)
            bh[k] += ((t >> k) & 1) ? e : 0.f;
    }

    float bs[16];
#pragma unroll
    for (int k = 0; k < 8; k++) bs[k] = ((tid >> k) & 1) ? s : 0.f;
#pragma unroll
    for (int k = 0; k < 7; k++) bs[k + 8] = bh[k];
    bs[15] = s;

#pragma unroll
    for (int q = 0; q < 16; q++) {
#pragma unroll
        for (int o = 16; o; o >>= 1)
            bs[q] += __shfl_xor_sync(0xffffffffu, bs[q], o);
    }
    __shared__ float red[8][16];
    if ((tid & 31) == 0) {
#pragma unroll
        for (int q = 0; q < 16; q++) red[tid >> 5][q] = bs[q];
    }
    __syncthreads();
    if (tid == 0) {
        float tot[16];
#pragma unroll
        for (int q = 0; q < 16; q++) {
            float v = 0.f;
#pragma unroll
            for (int w = 0; w < 8; w++) v += red[w][q];
            tot[q] = v;
        }
        float inv = 1.0f / tot[15];
#pragma unroll
        for (int k = 0; k < 15; k++)
            out_lw[(size_t)row * NBITS + (14 - k)] = 2.0f * tot[k] * inv - 1.0f;
    }
}

// ---------------------------------------------------------------------------
extern "C" void kernel_launch(void* const* d_in, const int* in_sizes, int n_in,
                              void* d_out, int out_size)
{
    const int*   ids    = (const int*)  d_in[0];
    const float* tensor = (const float*)d_in[1];
    const float* weight = (const float*)d_in[2];
    const float* wbit   = (const float*)d_in[3];

    float* out     = (float*)d_out;
    float* id_emb  = out;
    float* bit_emb = out + OFF_BIT;
    float* logit   = out + OFF_LOGIT;
    float* lw      = out + OFF_LW;

    id_embed_kernel <<<4096, 256>>>(ids, weight, id_emb);
    bit_embed_kernel<<<4096, 256>>>(ids, wbit, bit_emb);

    dim3 grid(VOCAB / 128, NTOK / 128);   // 250 x 32
    bf16x3_gemm_nt_kernel<<<grid, 256>>>(tensor, weight, logit);

    softmax_bits_kernel<<<NTOK, 256>>>(logit, lw);
}